// round 11
// baseline (speedup 1.0000x reference)
#include <cuda_runtime.h>
#include <cuda_bf16.h>
#include <mma.h>
#include <math.h>

using namespace nvcuda;

#define NB 8
#define NT 512
#define NS 128
#define NC 512
#define RR 19
#define NS1 129
#define NT1 513
#define MROWS (NB*NT*RR)
#define NEGF (-1e20f)

// ---------------- device scratch (allocation-free module globals) -----------
__device__ float g_lm_max[NB*NS1];
__device__ float g_lm_lse[NB*NS1];
__device__ float g_lm_p[(size_t)NB*NS1*NC];
__device__ float g_am_max[NB*NT];
__device__ float g_am_p[(size_t)NB*NT*NC];
__device__ float g_norm[(size_t)NB*NS1*NT];
__device__ float g_px[(size_t)NB*NS*NT1];
__device__ float g_py[(size_t)NB*NS1*NT];
__device__ float g_alpha[(size_t)NB*NS1*NT1];
__device__ float g_beta[(size_t)NB*NS1*NT1];
__device__ float g_total[NB];
__device__ float g_total2[NB];
__device__ float g_pxg[(size_t)NB*NS*NT1];
__device__ float g_pyg[(size_t)NB*NS1*NT];
__device__ int   g_sb[NB*NT];
__device__ __nv_bfloat16 g_A[(size_t)MROWS*NC];
__device__ __nv_bfloat16 g_W[NC*NC];
__device__ float g_logits[(size_t)MROWS*NC];
__device__ float g_px2[MROWS];
__device__ float g_py2[MROWS];
__device__ float g_pxf[(size_t)NB*NS*NT1];
__device__ float g_pyf[(size_t)NB*NS1*NT];

// ---------------- helpers ----------------
__device__ __forceinline__ float warpmax(float v){
  #pragma unroll
  for(int o=16;o>0;o>>=1) v=fmaxf(v,__shfl_xor_sync(0xffffffffu,v,o));
  return v;
}
__device__ __forceinline__ float warpsum(float v){
  #pragma unroll
  for(int o=16;o>0;o>>=1) v+=__shfl_xor_sync(0xffffffffu,v,o);
  return v;
}
__device__ __forceinline__ float lae(float a,float b){
  float mx=fmaxf(a,b), mn=fminf(a,b);
  return mx + log1pf(expf(mn-mx));
}

// ---------------- row stats ----------------
__global__ void k_lm_stats(const float* __restrict__ lm){
  int row = blockIdx.x*8 + (threadIdx.x>>5);
  int lane = threadIdx.x & 31;
  if(row >= NB*NS1) return;
  const float* L = lm + (size_t)row*NC;
  float v[16]; float mx = -3.4e38f;
  #pragma unroll
  for(int j=0;j<16;j++){ v[j]=L[lane+32*j]; mx=fmaxf(mx,v[j]); }
  mx = warpmax(mx);
  float s = 0.f;
  #pragma unroll
  for(int j=0;j<16;j++){ float e=expf(v[j]-mx); s+=e; g_lm_p[(size_t)row*NC+lane+32*j]=e; }
  s = warpsum(s);
  if(lane==0){ g_lm_max[row]=mx; g_lm_lse[row]=mx+logf(s); }
}

__global__ void k_am_stats(const float* __restrict__ am){
  int row = blockIdx.x*8 + (threadIdx.x>>5);
  int lane = threadIdx.x & 31;
  if(row >= NB*NT) return;
  const float* A = am + (size_t)row*NC;
  float v[16]; float mx = -3.4e38f;
  #pragma unroll
  for(int j=0;j<16;j++){ v[j]=A[lane+32*j]; mx=fmaxf(mx,v[j]); }
  mx = warpmax(mx);
  #pragma unroll
  for(int j=0;j<16;j++) g_am_p[(size_t)row*NC + lane+32*j] = expf(v[j]-mx);
  if(lane==0) g_am_max[row]=mx;
}

// ---------------- normalizers: log(sum_c lm_p*am_p) + maxes -----------------
__global__ void __launch_bounds__(1024) k_norm(){
  int b = blockIdx.z, s0 = blockIdx.y*32, t0 = blockIdx.x*32;
  __shared__ float Ls[32][33], As[32][33];
  int tx = threadIdx.x, ty = threadIdx.y;
  float acc = 0.f;
  for(int c0=0;c0<NC;c0+=32){
    int s = s0+ty;
    Ls[ty][tx] = (s<NS1)? g_lm_p[((size_t)b*NS1+s)*NC + c0+tx] : 0.f;
    As[ty][tx] = g_am_p[((size_t)b*NT + t0+ty)*NC + c0+tx];
    __syncthreads();
    #pragma unroll
    for(int c=0;c<32;c++) acc += Ls[ty][c]*As[tx][c];
    __syncthreads();
  }
  int s = s0+ty, t = t0+tx;
  if(s<NS1)
    g_norm[((size_t)b*NS1+s)*NT+t] = logf(acc) + g_lm_max[b*NS1+s] + g_am_max[b*NT+t];
}

// ---------------- smoothed px / py ----------------
__global__ void k_px(const float* __restrict__ am, const float* __restrict__ lm,
                     const int* __restrict__ tg){
  int idx = blockIdx.x*blockDim.x + threadIdx.x;
  if(idx >= NB*NS*NT1) return;
  int t = idx % NT1; int s = (idx/NT1) % NS; int b = idx/(NS*NT1);
  if(t == NT){ g_px[idx] = NEGF; return; }
  int sym = tg[b*NS+s];
  float lmv = lm[((size_t)b*NS1+s)*NC + sym];
  float amv = am[((size_t)b*NT+t)*NC + sym];
  float nrm = g_norm[((size_t)b*NS1+s)*NT + t];
  g_px[idx] = 0.75f*(amv+lmv-nrm) + 0.25f*(lmv - g_lm_lse[b*NS1+s]);
}

__global__ void k_py(const float* __restrict__ am, const float* __restrict__ lm){
  int idx = blockIdx.x*blockDim.x + threadIdx.x;
  if(idx >= NB*NS1*NT) return;
  int t = idx % NT; int s = (idx/NT) % NS1; int b = idx/(NS1*NT);
  float lmv = lm[((size_t)b*NS1+s)*NC];
  float amv = am[((size_t)b*NT+t)*NC];
  g_py[idx] = 0.75f*(amv+lmv-g_norm[idx]) + 0.25f*(lmv - g_lm_lse[b*NS1+s]);
}

// ---------------- lattice DP (diagonal wavefront, 1 barrier/step) ----------
// which==0: simple lattice (g_px/g_py), grid (NB,2) -> alpha+beta+g_total
// which==1: pruned lattice (g_pxf/g_pyf), grid (NB,1) -> alpha+g_total2
__global__ void k_dp(int which){
  const float* PXb = which ? g_pxf : g_px;
  const float* PYb = which ? g_pyf : g_py;
  float* TOT = which ? g_total2 : g_total;
  int b = blockIdx.x;
  int dir = blockIdx.y;       // 0 = forward(alpha), 1 = backward(beta)
  int s = threadIdx.x;        // 0..128
  __shared__ float buf[2][NS1];
  const float* PX = PXb + (size_t)b*NS*NT1;
  const float* PY = PYb + (size_t)b*NS1*NT;
  float p = NEGF;
  if(dir==0){
    float* AL = g_alpha + (size_t)b*NS1*NT1;
    const float* pxr = PX + (long long)(s-1)*NT1;   // valid only when s>0
    const float* pyr = PY + (long long)s*NT;
    for(int d=0; d<=NS+NT; ++d){
      int t = d - s;
      float np = p;
      if(t>=0 && t<=NT){
        if(s==0 && t==0) np = 0.f;
        else{
          float v1 = (s>0) ? buf[d&1][s-1] + pxr[t]   : NEGF;
          float v2 = (t>0) ? p          + pyr[t-1] : NEGF;
          np = lae(v1,v2);
        }
        AL[(size_t)s*NT1+t] = np;
      }
      buf[(d+1)&1][s] = np;
      p = np;
      __syncthreads();
    }
    if(s==NS) TOT[b] = p;
  } else {
    float* BE = g_beta + (size_t)b*NS1*NT1;
    const float* pxr = PX + (long long)s*NT1;        // valid only when s<NS
    const float* pyr = PY + (long long)s*NT;
    for(int d=0; d<=NS+NT; ++d){
      int t = NT - d + (NS - s);
      float np = p;
      if(t>=0 && t<=NT){
        if(s==NS && t==NT) np = 0.f;
        else{
          float v1 = (s<NS) ? buf[d&1][s+1] + pxr[t] : NEGF;
          float v2 = (t<NT) ? p          + pyr[t] : NEGF;
          np = lae(v1,v2);
        }
        BE[(size_t)s*NT1+t] = np;
      }
      buf[(d+1)&1][s] = np;
      p = np;
      __syncthreads();
    }
  }
}

// ---------------- occupancy grads ----------------
__global__ void k_pxgrad(){
  int idx = blockIdx.x*blockDim.x + threadIdx.x;
  if(idx >= NB*NS*NT1) return;
  int t = idx % NT1; int s = (idx/NT1) % NS; int b = idx/(NS*NT1);
  float a  = g_alpha[((size_t)b*NS1+s)*NT1 + t];
  float be = g_beta [((size_t)b*NS1+s+1)*NT1 + t];
  g_pxg[idx] = expf(a + g_px[idx] + be - g_total[b]);
}
__global__ void k_pygrad(){
  int idx = blockIdx.x*blockDim.x + threadIdx.x;
  if(idx >= NB*NS1*NT) return;
  int t = idx % NT; int s = (idx/NT) % NS1; int b = idx/(NS1*NT);
  float a  = g_alpha[((size_t)b*NS1+s)*NT1 + t];
  float be = g_beta [((size_t)b*NS1+s)*NT1 + t + 1];
  g_pyg[idx] = expf(a + g_py[idx] + be - g_total[b]);
}

// ---------------- pruning window argmax (cumsum-diff, first-max ties) -------
__global__ void k_sbegin(){
  int idx = blockIdx.x*blockDim.x + threadIdx.x;
  if(idx >= NB*NT) return;
  int b = idx / NT, t = idx % NT;
  float U[NS1+1];
  U[0] = 0.f;
  for(int s=0;s<=NS;s++){
    float u = g_pyg[((size_t)b*NS1+s)*NT + t];
    if(s < NS) u += g_pxg[((size_t)b*NS+s)*NT1 + t];
    U[s+1] = U[s] + u;
  }
  float best = -3.4e38f; int arg = 0;
  for(int w=0; w<=NS1-RR; w++){
    float v = U[w+RR] - U[w];
    if(v > best){ best = v; arg = w; }
  }
  g_sb[idx] = arg;
}

// suffix-min adjustment (fast_rnnt _adjust_pruning_lower_bound), exact int32
__global__ void k_adjust(){
  int b = threadIdx.x;
  if(b >= NB) return;
  int m = 1<<30, ym = 1<<30;
  for(int t=NT-1; t>=0; --t){
    int v = g_sb[b*NT+t];
    m = min(m, v);
    int y = (RR-1)*t - m;
    ym = min(ym, y);
    int yc = max(ym, 0);
    g_sb[b*NT+t] = (RR-1)*t - yc;
  }
}

// ---------------- joiner band build ----------------
__global__ void k_buildA(const float* __restrict__ am, const float* __restrict__ lm){
  int b = blockIdx.x / NT, t = blockIdx.x % NT;
  __shared__ float amr[NC];
  for(int c=threadIdx.x;c<NC;c+=256) amr[c]=am[((size_t)b*NT+t)*NC+c];
  __syncthreads();
  int sb = g_sb[b*NT+t];
  size_t base = (size_t)(b*NT+t)*RR;
  for(int j=0;j<RR;j++){
    const float* lr = lm + ((size_t)(b*NS1 + sb + j))*NC;
    for(int c=threadIdx.x;c<NC;c+=256)
      g_A[(base+j)*NC + c] = __float2bfloat16(tanhf(amr[c]+lr[c]));
  }
}

__global__ void k_convW(const float* __restrict__ w){
  int idx = blockIdx.x*blockDim.x + threadIdx.x;
  if(idx < NC*NC) g_W[idx] = __float2bfloat16(w[idx]);
}

// ---------------- joiner GEMM: logits = A(77824x512) @ W(512x512) -----------
__global__ void __launch_bounds__(256) k_gemm(){
  __shared__ __nv_bfloat16 As[128][40];   // 80B rows (16B aligned)
  __shared__ __nv_bfloat16 Bs[32][136];   // 272B rows (16B aligned)
  int bm = blockIdx.x * 128, bn = blockIdx.y * 128;
  int tid = threadIdx.x;
  int warp = tid>>5;
  int wm = warp & 1, wn = warp >> 1;      // wm:0..1 (64 rows), wn:0..3 (32 cols)
  wmma::fragment<wmma::accumulator,16,16,16,float> acc[4][2];
  #pragma unroll
  for(int i=0;i<4;i++)
    #pragma unroll
    for(int j=0;j<2;j++) wmma::fill_fragment(acc[i][j], 0.f);

  for(int k0=0;k0<NC;k0+=32){
    #pragma unroll
    for(int it=0; it<2; it++){
      int u = tid + 256*it;
      int row = u>>2, q = u&3;
      const uint4* src = (const uint4*)&g_A[(size_t)(bm+row)*NC + k0 + q*8];
      *(uint4*)&As[row][q*8] = *src;
    }
    #pragma unroll
    for(int it=0; it<2; it++){
      int u = tid + 256*it;
      int row = u>>4, q = u&15;
      const uint4* src = (const uint4*)&g_W[(size_t)(k0+row)*NC + bn + q*8];
      *(uint4*)&Bs[row][q*8] = *src;
    }
    __syncthreads();
    #pragma unroll
    for(int kk=0;kk<2;kk++){
      wmma::fragment<wmma::matrix_a,16,16,16,__nv_bfloat16,wmma::row_major> a[4];
      wmma::fragment<wmma::matrix_b,16,16,16,__nv_bfloat16,wmma::row_major> bfr[2];
      #pragma unroll
      for(int i=0;i<4;i++) wmma::load_matrix_sync(a[i], &As[wm*64+i*16][kk*16], 40);
      #pragma unroll
      for(int j=0;j<2;j++) wmma::load_matrix_sync(bfr[j], &Bs[kk*16][wn*32+j*16], 136);
      #pragma unroll
      for(int i=0;i<4;i++)
        #pragma unroll
        for(int j=0;j<2;j++) wmma::mma_sync(acc[i][j], a[i], bfr[j], acc[i][j]);
    }
    __syncthreads();
  }
  #pragma unroll
  for(int i=0;i<4;i++)
    #pragma unroll
    for(int j=0;j<2;j++)
      wmma::store_matrix_sync(&g_logits[(size_t)(bm + wm*64 + i*16)*NC + bn + wn*32 + j*16],
                              acc[i][j], NC, wmma::mem_row_major);
}

// ---------------- banded logsumexp + px2/py2 ----------------
__global__ void k_band(const int* __restrict__ tg, const float* __restrict__ bias){
  int wid = blockIdx.x*8 + (threadIdx.x>>5);
  int lane = threadIdx.x & 31;
  if(wid >= MROWS) return;
  int j = wid % RR; int t = (wid/RR)%NT; int b = wid/(RR*NT);
  const float* L = g_logits + (size_t)wid*NC;
  float v[16]; float mx = -3.4e38f;
  #pragma unroll
  for(int q=0;q<16;q++){ v[q]=L[lane+32*q] + bias[lane+32*q]; mx=fmaxf(mx,v[q]); }
  mx = warpmax(mx);
  float ss = 0.f;
  #pragma unroll
  for(int q=0;q<16;q++) ss += expf(v[q]-mx);
  ss = warpsum(ss);
  float lse = mx + logf(ss);
  int rng = g_sb[b*NT+t] + j;
  int sym = (rng < NS) ? tg[b*NS+rng] : 0;
  float vs = 0.f; int q0 = sym>>5;
  #pragma unroll
  for(int q=0;q<16;q++) if(q==q0) vs = v[q];
  vs = __shfl_sync(0xffffffffu, vs, sym&31);
  float v0 = __shfl_sync(0xffffffffu, v[0], 0);
  if(lane==0){ g_px2[wid] = vs - lse; g_py2[wid] = v0 - lse; }
}

// ---------------- scatter band to full lattice ----------------
__global__ void k_scx(){
  int idx = blockIdx.x*blockDim.x + threadIdx.x;
  if(idx >= NB*NS*NT1) return;
  int t = idx % NT1; int s = (idx/NT1) % NS; int b = idx/(NS*NT1);
  float v = NEGF;
  if(t < NT){
    int sb = g_sb[b*NT+t]; int j = s - sb;
    if(j>=0 && j<RR) v = g_px2[(size_t)(b*NT+t)*RR + j];
  }
  g_pxf[idx] = v;
}
__global__ void k_scy(){
  int idx = blockIdx.x*blockDim.x + threadIdx.x;
  if(idx >= NB*NS1*NT) return;
  int t = idx % NT; int s = (idx/NT) % NS1; int b = idx/(NS1*NT);
  int sb = g_sb[b*NT+t]; int j = s - sb;
  g_pyf[idx] = (j>=0 && j<RR) ? g_py2[(size_t)(b*NT+t)*RR + j] : NEGF;
}

// ---------------- final loss ----------------
__global__ void k_final(float* out){
  float a=0.f, c=0.f;
  for(int b=0;b<NB;b++){ a += g_total[b]; c += g_total2[b]; }
  out[0] = -(0.1f*a + c)/(float)NB;
}

extern "C" void kernel_launch(void* const* d_in, const int* in_sizes, int n_in,
                              void* d_out, int out_size) {
  const float* am  = (const float*)d_in[0];
  const float* lm  = (const float*)d_in[1];
  const int*   tg  = (const int*)  d_in[2];
  const float* jw  = (const float*)d_in[4];
  const float* jb  = (const float*)d_in[5];
  float* out = (float*)d_out;
  (void)in_sizes; (void)n_in; (void)out_size;

  k_lm_stats<<<(NB*NS1+7)/8, 256>>>(lm);
  k_am_stats<<<(NB*NT)/8, 256>>>(am);
  k_norm<<<dim3(NT/32, (NS1+31)/32, NB), dim3(32,32)>>>();
  k_px<<<(NB*NS*NT1+255)/256, 256>>>(am, lm, tg);
  k_py<<<(NB*NS1*NT+255)/256, 256>>>(am, lm);
  k_dp<<<dim3(NB,2), NS1>>>(0);
  k_pxgrad<<<(NB*NS*NT1+255)/256, 256>>>();
  k_pygrad<<<(NB*NS1*NT+255)/256, 256>>>();
  k_sbegin<<<(NB*NT+255)/256, 256>>>();
  k_adjust<<<1, NB>>>();
  k_buildA<<<NB*NT, 256>>>(am, lm);
  k_convW<<<(NC*NC+255)/256, 256>>>(jw);
  k_gemm<<<dim3(MROWS/128, NC/128), 256>>>();
  k_band<<<MROWS/8, 256>>>(tg, jb);
  k_scx<<<(NB*NS*NT1+255)/256, 256>>>();
  k_scy<<<(NB*NS1*NT+255)/256, 256>>>();
  k_dp<<<dim3(NB,1), NS1>>>(1);
  k_final<<<1,1>>>(out);
}

// round 13
// speedup vs baseline: 1.1251x; 1.1251x over previous
#include <cuda_runtime.h>
#include <cuda_bf16.h>
#include <mma.h>
#include <math.h>
#include <cstdint>

using namespace nvcuda;

#define NB 8
#define NT 512
#define NS 128
#define NC 512
#define RR 19
#define NS1 129
#define NT1 513
#define MROWS (NB*NT*RR)
#define NEGF (-1e20f)

// ---------------- device scratch (allocation-free module globals) -----------
__device__ float g_lm_max[NB*NS1];
__device__ float g_lm_lse[NB*NS1];
__device__ float g_lm_p[(size_t)NB*NS1*NC];
__device__ float g_am_max[NB*NT];
__device__ float g_am_p[(size_t)NB*NT*NC];
__device__ float g_norm[(size_t)NB*NS1*NT];
__device__ float g_px[(size_t)NB*NS*NT1];
__device__ float g_py[(size_t)NB*NS1*NT];
__device__ float g_alpha[(size_t)NB*NS1*NT1];
__device__ float g_beta[(size_t)NB*NS1*NT1];
__device__ float g_total[NB];
__device__ float g_total2[NB];
__device__ float g_pxg[(size_t)NB*NS*NT1];
__device__ float g_pyg[(size_t)NB*NS1*NT];
__device__ int   g_sb[NB*NT];
__device__ __nv_bfloat16 g_A[(size_t)MROWS*NC];
__device__ __nv_bfloat16 g_W[NC*NC];
__device__ float g_pmax[(size_t)MROWS*4];
__device__ float g_psum[(size_t)MROWS*4];
__device__ float g_pxv[MROWS];
__device__ float g_pyv[MROWS];
__device__ float g_px2[MROWS];
__device__ float g_py2[MROWS];
__device__ float g_pxf[(size_t)NB*NS*NT1];
__device__ float g_pyf[(size_t)NB*NS1*NT];

// ---------------- helpers ----------------
__device__ __forceinline__ float warpmax(float v){
  #pragma unroll
  for(int o=16;o>0;o>>=1) v=fmaxf(v,__shfl_xor_sync(0xffffffffu,v,o));
  return v;
}
__device__ __forceinline__ float warpsum(float v){
  #pragma unroll
  for(int o=16;o>0;o>>=1) v+=__shfl_xor_sync(0xffffffffu,v,o);
  return v;
}
__device__ __forceinline__ float lae(float a,float b){
  float mx=fmaxf(a,b), mn=fminf(a,b);
  return mx + log1pf(expf(mn-mx));
}
__device__ __forceinline__ void cp16(uint32_t dst, const void* src){
  asm volatile("cp.async.cg.shared.global [%0], [%1], 16;" :: "r"(dst), "l"(src));
}

// ---------------- merged row stats (lm rows then am rows) -------------------
__global__ void k_stats(const float* __restrict__ lm, const float* __restrict__ am){
  int row = blockIdx.x*8 + (threadIdx.x>>5);
  int lane = threadIdx.x & 31;
  if(row < NB*NS1){
    const float* L = lm + (size_t)row*NC;
    float v[16]; float mx = -3.4e38f;
    #pragma unroll
    for(int j=0;j<16;j++){ v[j]=L[lane+32*j]; mx=fmaxf(mx,v[j]); }
    mx = warpmax(mx);
    float s = 0.f;
    #pragma unroll
    for(int j=0;j<16;j++){ float e=expf(v[j]-mx); s+=e; g_lm_p[(size_t)row*NC+lane+32*j]=e; }
    s = warpsum(s);
    if(lane==0){ g_lm_max[row]=mx; g_lm_lse[row]=mx+logf(s); }
  } else {
    int r = row - NB*NS1;
    if(r >= NB*NT) return;
    const float* A = am + (size_t)r*NC;
    float v[16]; float mx = -3.4e38f;
    #pragma unroll
    for(int j=0;j<16;j++){ v[j]=A[lane+32*j]; mx=fmaxf(mx,v[j]); }
    mx = warpmax(mx);
    #pragma unroll
    for(int j=0;j<16;j++) g_am_p[(size_t)r*NC + lane+32*j] = expf(v[j]-mx);
    if(lane==0) g_am_max[r]=mx;
  }
}

// ---------------- normalizers: 64x64 tile, 4x4 register blocking ------------
__global__ void __launch_bounds__(256) k_norm(){
  int b = blockIdx.z, s0 = blockIdx.y*64, t0 = blockIdx.x*64;
  __shared__ float Ls[64][17], Am[64][17];
  int tid = threadIdx.x;
  int ty = tid>>4, tx = tid&15;
  float acc[4][4];
  #pragma unroll
  for(int i=0;i<4;i++)
    #pragma unroll
    for(int j=0;j<4;j++) acc[i][j]=0.f;

  int lr = tid>>2, lq = (tid&3)*4;
  for(int c0=0;c0<NC;c0+=16){
    {
      int s = s0 + lr;
      float4 v = (s<NS1) ? *(const float4*)&g_lm_p[((size_t)b*NS1+s)*NC + c0 + lq]
                         : make_float4(0.f,0.f,0.f,0.f);
      Ls[lr][lq]=v.x; Ls[lr][lq+1]=v.y; Ls[lr][lq+2]=v.z; Ls[lr][lq+3]=v.w;
    }
    {
      float4 v = *(const float4*)&g_am_p[((size_t)b*NT + t0 + lr)*NC + c0 + lq];
      Am[lr][lq]=v.x; Am[lr][lq+1]=v.y; Am[lr][lq+2]=v.z; Am[lr][lq+3]=v.w;
    }
    __syncthreads();
    #pragma unroll
    for(int c=0;c<16;c++){
      float a0=Ls[ty*4+0][c], a1=Ls[ty*4+1][c], a2=Ls[ty*4+2][c], a3=Ls[ty*4+3][c];
      float e0=Am[tx*4+0][c], e1=Am[tx*4+1][c], e2=Am[tx*4+2][c], e3=Am[tx*4+3][c];
      acc[0][0]+=a0*e0; acc[0][1]+=a0*e1; acc[0][2]+=a0*e2; acc[0][3]+=a0*e3;
      acc[1][0]+=a1*e0; acc[1][1]+=a1*e1; acc[1][2]+=a1*e2; acc[1][3]+=a1*e3;
      acc[2][0]+=a2*e0; acc[2][1]+=a2*e1; acc[2][2]+=a2*e2; acc[2][3]+=a2*e3;
      acc[3][0]+=a3*e0; acc[3][1]+=a3*e1; acc[3][2]+=a3*e2; acc[3][3]+=a3*e3;
    }
    __syncthreads();
  }
  #pragma unroll
  for(int i=0;i<4;i++){
    int s = s0 + ty*4 + i;
    if(s >= NS1) continue;
    float lmx = g_lm_max[b*NS1+s];
    #pragma unroll
    for(int j=0;j<4;j++){
      int t = t0 + tx*4 + j;
      g_norm[((size_t)b*NS1+s)*NT+t] = logf(acc[i][j]) + lmx + g_am_max[b*NT+t];
    }
  }
}

// ---------------- smoothed px / py (merged) ----------------
__global__ void k_pxy(const float* __restrict__ am, const float* __restrict__ lm,
                      const int* __restrict__ tg){
  int idx = blockIdx.x*blockDim.x + threadIdx.x;
  const int N1 = NB*NS*NT1;
  if(idx < N1){
    int t = idx % NT1; int s = (idx/NT1) % NS; int b = idx/(NS*NT1);
    if(t == NT){ g_px[idx] = NEGF; return; }
    int sym = tg[b*NS+s];
    float lmv = lm[((size_t)b*NS1+s)*NC + sym];
    float amv = am[((size_t)b*NT+t)*NC + sym];
    float nrm = g_norm[((size_t)b*NS1+s)*NT + t];
    g_px[idx] = 0.75f*(amv+lmv-nrm) + 0.25f*(lmv - g_lm_lse[b*NS1+s]);
  } else {
    int k = idx - N1;
    if(k >= NB*NS1*NT) return;
    int t = k % NT; int s = (k/NT) % NS1; int b = k/(NS1*NT);
    float lmv = lm[((size_t)b*NS1+s)*NC];
    float amv = am[((size_t)b*NT+t)*NC];
    g_py[k] = 0.75f*(amv+lmv-g_norm[k]) + 0.25f*(lmv - g_lm_lse[b*NS1+s]);
  }
}

// ---------------- lattice DP (diagonal wavefront) ----------
__global__ void k_dp(int which){
  const float* PXb = which ? g_pxf : g_px;
  const float* PYb = which ? g_pyf : g_py;
  float* TOT = which ? g_total2 : g_total;
  int b = blockIdx.x;
  int dir = blockIdx.y;
  int s = threadIdx.x;
  __shared__ float buf[2][NS1];
  const float* PX = PXb + (size_t)b*NS*NT1;
  const float* PY = PYb + (size_t)b*NS1*NT;
  float p = NEGF;
  if(dir==0){
    float* AL = g_alpha + (size_t)b*NS1*NT1;
    const float* pxr = PX + (long long)(s-1)*NT1;
    const float* pyr = PY + (long long)s*NT;
    for(int d=0; d<=NS+NT; ++d){
      int t = d - s;
      float np = p;
      if(t>=0 && t<=NT){
        if(s==0 && t==0) np = 0.f;
        else{
          float v1 = (s>0) ? buf[d&1][s-1] + pxr[t]   : NEGF;
          float v2 = (t>0) ? p          + pyr[t-1] : NEGF;
          np = lae(v1,v2);
        }
        if(!which) AL[(size_t)s*NT1+t] = np;
      }
      buf[(d+1)&1][s] = np;
      p = np;
      __syncthreads();
    }
    if(s==NS) TOT[b] = p;
  } else {
    float* BE = g_beta + (size_t)b*NS1*NT1;
    const float* pxr = PX + (long long)s*NT1;
    const float* pyr = PY + (long long)s*NT;
    for(int d=0; d<=NS+NT; ++d){
      int t = NT - d + (NS - s);
      float np = p;
      if(t>=0 && t<=NT){
        if(s==NS && t==NT) np = 0.f;
        else{
          float v1 = (s<NS) ? buf[d&1][s+1] + pxr[t] : NEGF;
          float v2 = (t<NT) ? p          + pyr[t] : NEGF;
          np = lae(v1,v2);
        }
        BE[(size_t)s*NT1+t] = np;
      }
      buf[(d+1)&1][s] = np;
      p = np;
      __syncthreads();
    }
  }
}

// ---------------- occupancy grads (merged) ----------------
__global__ void k_grads(){
  int idx = blockIdx.x*blockDim.x + threadIdx.x;
  const int N1 = NB*NS*NT1;
  if(idx < N1){
    int t = idx % NT1; int s = (idx/NT1) % NS; int b = idx/(NS*NT1);
    float a  = g_alpha[((size_t)b*NS1+s)*NT1 + t];
    float be = g_beta [((size_t)b*NS1+s+1)*NT1 + t];
    g_pxg[idx] = expf(a + g_px[idx] + be - g_total[b]);
  } else {
    int k = idx - N1;
    if(k >= NB*NS1*NT) return;
    int t = k % NT; int s = (k/NT) % NS1; int b = k/(NS1*NT);
    float a  = g_alpha[((size_t)b*NS1+s)*NT1 + t];
    float be = g_beta [((size_t)b*NS1+s)*NT1 + t + 1];
    g_pyg[k] = expf(a + g_py[k] + be - g_total[b]);
  }
}

// ---------------- pruning window argmax ----------------
__global__ void k_sbegin(){
  int idx = blockIdx.x*blockDim.x + threadIdx.x;
  if(idx >= NB*NT) return;
  int b = idx / NT, t = idx % NT;
  float U[NS1+1];
  U[0] = 0.f;
  for(int s=0;s<=NS;s++){
    float u = g_pyg[((size_t)b*NS1+s)*NT + t];
    if(s < NS) u += g_pxg[((size_t)b*NS+s)*NT1 + t];
    U[s+1] = U[s] + u;
  }
  float best = -3.4e38f; int arg = 0;
  for(int w=0; w<=NS1-RR; w++){
    float v = U[w+RR] - U[w];
    if(v > best){ best = v; arg = w; }
  }
  g_sb[idx] = arg;
}

__global__ void k_adjust(){
  int b = threadIdx.x;
  if(b >= NB) return;
  int m = 1<<30, ym = 1<<30;
  for(int t=NT-1; t>=0; --t){
    int v = g_sb[b*NT+t];
    m = min(m, v);
    int y = (RR-1)*t - m;
    ym = min(ym, y);
    int yc = max(ym, 0);
    g_sb[b*NT+t] = (RR-1)*t - yc;
  }
}

// ---------------- joiner band build (bf16x2 stores) ----------------
__global__ void k_buildA(const float* __restrict__ am, const float* __restrict__ lm){
  int b = blockIdx.x / NT, t = blockIdx.x % NT;
  __shared__ float amr[NC];
  for(int c=threadIdx.x;c<NC;c+=256) amr[c]=am[((size_t)b*NT+t)*NC+c];
  __syncthreads();
  int sb = g_sb[b*NT+t];
  size_t base = (size_t)(b*NT+t)*RR;
  int c = threadIdx.x*2;   // 0..510
  for(int j=0;j<RR;j++){
    const float* lr = lm + ((size_t)(b*NS1 + sb + j))*NC;
    float2 lv = *(const float2*)&lr[c];
    __nv_bfloat162 o;
    o.x = __float2bfloat16(tanhf(amr[c]   + lv.x));
    o.y = __float2bfloat16(tanhf(amr[c+1] + lv.y));
    *(__nv_bfloat162*)&g_A[(base+j)*NC + c] = o;
  }
}

__global__ void k_convW(const float* __restrict__ w){
  int idx = blockIdx.x*blockDim.x + threadIdx.x;
  if(idx < NC*NC) g_W[idx] = __float2bfloat16(w[idx]);
}

// ---- joiner GEMM + fused band epilogue -------------------------------------
// grid (4, 608): bn = blockIdx.x*128, bm = blockIdx.y*128
#define AP 40
#define BP 136
#define AST (128*AP)
#define BST (32*BP)
__global__ void __launch_bounds__(256) k_gemm(const int* __restrict__ tg,
                                              const float* __restrict__ bias){
  __shared__ __align__(16) char sbuf[(2*AST + 2*BST)*2];   // 37888 B
  __nv_bfloat16* As = (__nv_bfloat16*)sbuf;
  __nv_bfloat16* Bs = (__nv_bfloat16*)(sbuf + 2*AST*2);
  int bn = blockIdx.x*128, bm = blockIdx.y*128;
  int tid = threadIdx.x, warp = tid>>5, lane = tid&31;
  int wm = warp & 1, wn = warp >> 1;
  uint32_t asb = (uint32_t)__cvta_generic_to_shared(As);
  uint32_t bsb = (uint32_t)__cvta_generic_to_shared(Bs);

  wmma::fragment<wmma::accumulator,16,16,16,float> acc[4][2];
  #pragma unroll
  for(int i=0;i<4;i++)
    #pragma unroll
    for(int j=0;j<2;j++) wmma::fill_fragment(acc[i][j], 0.f);

  // stage loader
  auto loadst = [&](int ki, int st){
    #pragma unroll
    for(int it=0;it<2;it++){
      int v = tid + it*256, row = v>>2, q = v&3;
      cp16(asb + (st*AST + row*AP)*2 + q*16,
           &g_A[(size_t)(bm+row)*NC + ki*32 + q*8]);
    }
    #pragma unroll
    for(int it=0;it<2;it++){
      int v = tid + it*256, row = v>>4, q = v&15;
      cp16(bsb + (st*BST + row*BP)*2 + q*16,
           &g_W[(size_t)(ki*32+row)*NC + bn + q*8]);
    }
    asm volatile("cp.async.commit_group;");
  };

  loadst(0,0);
  for(int k=0;k<16;k++){
    int cur = k&1;
    if(k<15){
      loadst(k+1, cur^1);
      asm volatile("cp.async.wait_group 1;");
    } else {
      asm volatile("cp.async.wait_group 0;");
    }
    __syncthreads();
    __nv_bfloat16* Ac = As + cur*AST;
    __nv_bfloat16* Bc = Bs + cur*BST;
    #pragma unroll
    for(int kk=0;kk<2;kk++){
      wmma::fragment<wmma::matrix_a,16,16,16,__nv_bfloat16,wmma::row_major> a[4];
      wmma::fragment<wmma::matrix_b,16,16,16,__nv_bfloat16,wmma::row_major> bfr[2];
      #pragma unroll
      for(int i=0;i<4;i++) wmma::load_matrix_sync(a[i], &Ac[(wm*64+i*16)*AP + kk*16], AP);
      #pragma unroll
      for(int j=0;j<2;j++) wmma::load_matrix_sync(bfr[j], &Bc[(kk*16)*BP + wn*32 + j*16], BP);
      #pragma unroll
      for(int i=0;i<4;i++)
        #pragma unroll
        for(int j=0;j<2;j++) wmma::mma_sync(acc[i][j], a[i], bfr[j], acc[i][j]);
    }
    __syncthreads();
  }

  // ---- fused band epilogue: per-block partial logsumexp + extraction ----
  float* Sg = (float*)sbuf;      // [64][132] staging (33792 B <= 37888)
  #pragma unroll
  for(int ph=0; ph<2; ph++){
    if(wm == ph){
      #pragma unroll
      for(int i=0;i<4;i++)
        #pragma unroll
        for(int j=0;j<2;j++)
          wmma::store_matrix_sync(&Sg[(i*16)*132 + wn*32 + j*16], acc[i][j], 132,
                                  wmma::mem_row_major);
    }
    __syncthreads();
    #pragma unroll
    for(int q=0;q<8;q++){
      int r = warp*8 + q;
      float4 v4 = *(float4*)&Sg[r*132 + lane*4];
      float4 b4 = *(const float4*)&bias[bn + lane*4];
      float x0=v4.x+b4.x, x1=v4.y+b4.y, x2=v4.z+b4.z, x3=v4.w+b4.w;
      float mx = warpmax(fmaxf(fmaxf(x0,x1),fmaxf(x2,x3)));
      float ss = warpsum(expf(x0-mx)+expf(x1-mx)+expf(x2-mx)+expf(x3-mx));
      if(lane==0){
        int gr = bm + ph*64 + r;
        g_pmax[(size_t)gr*4 + blockIdx.x] = mx;
        g_psum[(size_t)gr*4 + blockIdx.x] = ss;
        int j = gr % RR; int bt = gr/RR; int b = bt/NT;
        int rng = g_sb[bt] + j;
        int sym = (rng < NS) ? tg[b*NS + rng] : 0;
        int sc = sym - bn;
        if(sc >= 0 && sc < 128) g_pxv[gr] = Sg[r*132 + sc] + bias[sym];
        if(bn == 0)             g_pyv[gr] = Sg[r*132]      + bias[0];
      }
    }
    __syncthreads();
  }
}

// ---------------- combine N-partials into px2/py2 ----------------
__global__ void k_comb(){
  int idx = blockIdx.x*blockDim.x + threadIdx.x;
  if(idx >= MROWS) return;
  float4 m4 = *(const float4*)&g_pmax[(size_t)idx*4];
  float4 s4 = *(const float4*)&g_psum[(size_t)idx*4];
  float M = fmaxf(fmaxf(m4.x,m4.y), fmaxf(m4.z,m4.w));
  float S = s4.x*expf(m4.x-M) + s4.y*expf(m4.y-M) + s4.z*expf(m4.z-M) + s4.w*expf(m4.w-M);
  float lse = M + logf(S);
  g_px2[idx] = g_pxv[idx] - lse;
  g_py2[idx] = g_pyv[idx] - lse;
}

// ---------------- scatter band to full lattice (merged) ----------------
__global__ void k_scatter(){
  int idx = blockIdx.x*blockDim.x + threadIdx.x;
  const int N1 = NB*NS*NT1;
  if(idx < N1){
    int t = idx % NT1; int s = (idx/NT1) % NS; int b = idx/(NS*NT1);
    float v = NEGF;
    if(t < NT){
      int sb = g_sb[b*NT+t]; int j = s - sb;
      if(j>=0 && j<RR) v = g_px2[(size_t)(b*NT+t)*RR + j];
    }
    g_pxf[idx] = v;
  } else {
    int k = idx - N1;
    if(k >= NB*NS1*NT) return;
    int t = k % NT; int s = (k/NT) % NS1; int b = k/(NS1*NT);
    int sb = g_sb[b*NT+t]; int j = s - sb;
    g_pyf[k] = (j>=0 && j<RR) ? g_py2[(size_t)(b*NT+t)*RR + j] : NEGF;
  }
}

// ---------------- final loss ----------------
__global__ void k_final(float* out){
  float a=0.f, c=0.f;
  for(int b=0;b<NB;b++){ a += g_total[b]; c += g_total2[b]; }
  out[0] = -(0.1f*a + c)/(float)NB;
}

extern "C" void kernel_launch(void* const* d_in, const int* in_sizes, int n_in,
                              void* d_out, int out_size) {
  const float* am  = (const float*)d_in[0];
  const float* lm  = (const float*)d_in[1];
  const int*   tg  = (const int*)  d_in[2];
  const float* jw  = (const float*)d_in[4];
  const float* jb  = (const float*)d_in[5];
  float* out = (float*)d_out;
  (void)in_sizes; (void)n_in; (void)out_size;

  const int NPXY = NB*NS*NT1 + NB*NS1*NT;

  k_convW<<<(NC*NC+255)/256, 256>>>(jw);
  k_stats<<<(NB*NS1 + NB*NT + 7)/8, 256>>>(lm, am);
  k_norm<<<dim3(NT/64, (NS1+63)/64, NB), 256>>>();
  k_pxy<<<(NPXY+255)/256, 256>>>(am, lm, tg);
  k_dp<<<dim3(NB,2), NS1>>>(0);
  k_grads<<<(NPXY+255)/256, 256>>>();
  k_sbegin<<<(NB*NT+255)/256, 256>>>();
  k_adjust<<<1, NB>>>();
  k_buildA<<<NB*NT, 256>>>(am, lm);
  k_gemm<<<dim3(4, MROWS/128), 256>>>(tg, jb);
  k_comb<<<(MROWS+255)/256, 256>>>();
  k_scatter<<<(NPXY+255)/256, 256>>>();
  k_dp<<<dim3(NB,1), NS1>>>(1);
  k_final<<<1,1>>>(out);
}

// round 14
// speedup vs baseline: 1.5112x; 1.3431x over previous
#include <cuda_runtime.h>
#include <cuda_bf16.h>
#include <mma.h>
#include <math.h>
#include <cstdint>

using namespace nvcuda;

#define NB 8
#define NT 512
#define NS 128
#define NC 512
#define RR 19
#define NS1 129
#define NT1 513
#define MROWS (NB*NT*RR)
#define NEGF (-1e20f)

// ---------------- device scratch (allocation-free module globals) -----------
__device__ float g_lm_max[NB*NS1];
__device__ float g_lm_lse[NB*NS1];
__device__ float g_lm_p[(size_t)NB*NS1*NC];
__device__ float g_am_max[NB*NT];
__device__ float g_am_p[(size_t)NB*NT*NC];
__device__ float g_px[(size_t)NB*NS*NT1];
__device__ float g_py[(size_t)NB*NS1*NT];
__device__ float g_alpha[(size_t)NB*NS1*NT1];
__device__ float g_beta[(size_t)NB*NS1*NT1];
__device__ float g_total[NB];
__device__ float g_total2[NB];
__device__ float g_pxg[(size_t)NB*NS*NT1];
__device__ float g_pyg[(size_t)NB*NS1*NT];
__device__ int   g_sb[NB*NT];
__device__ __nv_bfloat16 g_A[(size_t)MROWS*NC];
__device__ __nv_bfloat16 g_W[NC*NC];
__device__ float g_pmax[(size_t)MROWS*4];
__device__ float g_psum[(size_t)MROWS*4];
__device__ float g_pxv[MROWS];
__device__ float g_pyv[MROWS];
__device__ float g_pxf[(size_t)NB*NS*NT1];
__device__ float g_pyf[(size_t)NB*NS1*NT];

// ---------------- helpers ----------------
__device__ __forceinline__ float warpmax(float v){
  #pragma unroll
  for(int o=16;o>0;o>>=1) v=fmaxf(v,__shfl_xor_sync(0xffffffffu,v,o));
  return v;
}
__device__ __forceinline__ float warpsum(float v){
  #pragma unroll
  for(int o=16;o>0;o>>=1) v+=__shfl_xor_sync(0xffffffffu,v,o);
  return v;
}
// fast logaddexp via MUFU ex2/lg2 (err ~1e-7 abs, fine for 1e-3 tolerance)
__device__ __forceinline__ float lae2(float a,float b){
  float mx=fmaxf(a,b), mn=fminf(a,b);
  float d = (mn-mx)*1.4426950408889634f;
  float e; asm("ex2.approx.f32 %0, %1;" : "=f"(e) : "f"(d));
  float l; asm("lg2.approx.f32 %0, %1;" : "=f"(l) : "f"(1.0f+e));
  return mx + l*0.6931471805599453f;
}
__device__ __forceinline__ float tanh_ap(float x){
  float r; asm("tanh.approx.f32 %0, %1;" : "=f"(r) : "f"(x)); return r;
}
__device__ __forceinline__ void cp16(uint32_t dst, const void* src){
  asm volatile("cp.async.cg.shared.global [%0], [%1], 16;" :: "r"(dst), "l"(src));
}

// ---------------- merged row stats (lm rows then am rows) -------------------
__global__ void k_stats(const float* __restrict__ lm, const float* __restrict__ am){
  int row = blockIdx.x*8 + (threadIdx.x>>5);
  int lane = threadIdx.x & 31;
  if(row < NB*NS1){
    const float* L = lm + (size_t)row*NC;
    float v[16]; float mx = -3.4e38f;
    #pragma unroll
    for(int j=0;j<16;j++){ v[j]=L[lane+32*j]; mx=fmaxf(mx,v[j]); }
    mx = warpmax(mx);
    float s = 0.f;
    #pragma unroll
    for(int j=0;j<16;j++){ float e=expf(v[j]-mx); s+=e; g_lm_p[(size_t)row*NC+lane+32*j]=e; }
    s = warpsum(s);
    if(lane==0){ g_lm_max[row]=mx; g_lm_lse[row]=mx+logf(s); }
  } else {
    int r = row - NB*NS1;
    if(r >= NB*NT) return;
    const float* A = am + (size_t)r*NC;
    float v[16]; float mx = -3.4e38f;
    #pragma unroll
    for(int j=0;j<16;j++){ v[j]=A[lane+32*j]; mx=fmaxf(mx,v[j]); }
    mx = warpmax(mx);
    #pragma unroll
    for(int j=0;j<16;j++) g_am_p[(size_t)r*NC + lane+32*j] = expf(v[j]-mx);
    if(lane==0) g_am_max[r]=mx;
  }
}

// ---- normalizers (64x64 tile, 4x4 reg blocking) + fused px/py epilogue -----
__global__ void __launch_bounds__(256) k_norm(const float* __restrict__ am,
                                              const float* __restrict__ lm,
                                              const int* __restrict__ tg){
  int b = blockIdx.z, s0 = blockIdx.y*64, t0 = blockIdx.x*64;
  __shared__ float Ls[64][17], Am[64][17];
  int tid = threadIdx.x;
  int ty = tid>>4, tx = tid&15;
  float acc[4][4];
  #pragma unroll
  for(int i=0;i<4;i++)
    #pragma unroll
    for(int j=0;j<4;j++) acc[i][j]=0.f;

  int lr = tid>>2, lq = (tid&3)*4;
  for(int c0=0;c0<NC;c0+=16){
    {
      int s = s0 + lr;
      float4 v = (s<NS1) ? *(const float4*)&g_lm_p[((size_t)b*NS1+s)*NC + c0 + lq]
                         : make_float4(0.f,0.f,0.f,0.f);
      Ls[lr][lq]=v.x; Ls[lr][lq+1]=v.y; Ls[lr][lq+2]=v.z; Ls[lr][lq+3]=v.w;
    }
    {
      float4 v = *(const float4*)&g_am_p[((size_t)b*NT + t0 + lr)*NC + c0 + lq];
      Am[lr][lq]=v.x; Am[lr][lq+1]=v.y; Am[lr][lq+2]=v.z; Am[lr][lq+3]=v.w;
    }
    __syncthreads();
    #pragma unroll
    for(int c=0;c<16;c++){
      float a0=Ls[ty*4+0][c], a1=Ls[ty*4+1][c], a2=Ls[ty*4+2][c], a3=Ls[ty*4+3][c];
      float e0=Am[tx*4+0][c], e1=Am[tx*4+1][c], e2=Am[tx*4+2][c], e3=Am[tx*4+3][c];
      acc[0][0]+=a0*e0; acc[0][1]+=a0*e1; acc[0][2]+=a0*e2; acc[0][3]+=a0*e3;
      acc[1][0]+=a1*e0; acc[1][1]+=a1*e1; acc[1][2]+=a1*e2; acc[1][3]+=a1*e3;
      acc[2][0]+=a2*e0; acc[2][1]+=a2*e1; acc[2][2]+=a2*e2; acc[2][3]+=a2*e3;
      acc[3][0]+=a3*e0; acc[3][1]+=a3*e1; acc[3][2]+=a3*e2; acc[3][3]+=a3*e3;
    }
    __syncthreads();
  }
  #pragma unroll
  for(int i=0;i<4;i++){
    int s = s0 + ty*4 + i;
    if(s >= NS1) continue;
    float lmx = g_lm_max[b*NS1+s];
    float lse = g_lm_lse[b*NS1+s];
    float lm0 = lm[((size_t)b*NS1+s)*NC];
    int sym = (s<NS) ? tg[b*NS+s] : 0;
    float lms = (s<NS) ? lm[((size_t)b*NS1+s)*NC + sym] : 0.f;
    #pragma unroll
    for(int j=0;j<4;j++){
      int t = t0 + tx*4 + j;
      float nrm = logf(acc[i][j]) + lmx + g_am_max[b*NT+t];
      float am0 = am[((size_t)b*NT+t)*NC];
      g_py[((size_t)b*NS1+s)*NT+t] = 0.75f*(am0+lm0-nrm) + 0.25f*(lm0-lse);
      if(s<NS){
        float ams = am[((size_t)b*NT+t)*NC + sym];
        g_px[((size_t)b*NS+s)*NT1+t] = 0.75f*(ams+lms-nrm) + 0.25f*(lms-lse);
      }
    }
  }
}

// ---------------- W conversion + px t=NT sentinel init ----------------------
__global__ void k_convW(const float* __restrict__ w){
  int idx = blockIdx.x*blockDim.x + threadIdx.x;
  if(idx < NC*NC) g_W[idx] = __float2bfloat16(w[idx]);
  if(idx < NB*NS) g_px[(size_t)idx*NT1 + NT] = NEGF;
}

// ---------------- lattice DP: wavefront, 2-deep prefetch, fast lae ----------
__global__ void k_dp(int which){
  const float* PXb = which ? g_pxf : g_px;
  const float* PYb = which ? g_pyf : g_py;
  float* TOT = which ? g_total2 : g_total;
  int b = blockIdx.x;
  int dir = blockIdx.y;
  int s = threadIdx.x;
  __shared__ float buf[2][NS1];
  const float* PX = PXb + (size_t)b*NS*NT1;
  const float* PY = PYb + (size_t)b*NS1*NT;
  float p = NEGF;
  if(dir==0){
    float* AL = g_alpha + (size_t)b*NS1*NT1;
    const float* pxr = PX + (size_t)((s>=1)?(s-1):0)*NT1;   // row s-1 (unused if s==0)
    const float* pyr = PY + (size_t)s*NT;
    bool hasx = (s>=1);
    // step d needs X=pxr[t], Y=pyr[t-1], t=d-s. 2-deep register pipeline.
    int tA = -s;
    int ci; float x0,x1,x2,y0,y1,y2;
    ci = tA<0?0:(tA>NT?NT:tA);           x0 = __ldg(&pxr[ci]);
    ci = tA-1<0?0:(tA-1>NT-1?NT-1:tA-1); y0 = __ldg(&pyr[ci]);
    ci = tA+1<0?0:(tA+1>NT?NT:tA+1);     x1 = __ldg(&pxr[ci]);
    ci = tA<0?0:(tA>NT-1?NT-1:tA);       y1 = __ldg(&pyr[ci]);
    for(int d=0; d<=NS+NT; ++d){
      int t = d - s;
      int tp = t+2;
      ci = tp<0?0:(tp>NT?NT:tp);           x2 = __ldg(&pxr[ci]);
      ci = tp-1<0?0:(tp-1>NT-1?NT-1:tp-1); y2 = __ldg(&pyr[ci]);
      float np = p;
      if(t>=0 && t<=NT){
        if(s==0 && t==0) np = 0.f;
        else{
          float v1 = hasx ? buf[d&1][s-1] + x0 : NEGF;
          float v2 = (t>0) ? p + y0 : NEGF;
          np = lae2(v1,v2);
        }
        if(!which) AL[(size_t)s*NT1+t] = np;
      }
      buf[(d+1)&1][s] = np;
      p = np;
      x0=x1; x1=x2; y0=y1; y1=y2;
      __syncthreads();
    }
    if(s==NS) TOT[b] = p;
  } else {
    float* BE = g_beta + (size_t)b*NS1*NT1;
    const float* pxr = PX + (size_t)((s<NS)?s:0)*NT1;       // row s (unused if s==NS)
    const float* pyr = PY + (size_t)s*NT;
    bool hasx = (s<NS);
    // step d: t = NT - d + (NS - s); needs X=pxr[t], Y=pyr[t]
    int tA = NT + NS - s;
    int ci; float x0,x1,x2,y0,y1,y2;
    ci = tA<0?0:(tA>NT?NT:tA);       x0 = __ldg(&pxr[ci]);
    ci = tA<0?0:(tA>NT-1?NT-1:tA);   y0 = __ldg(&pyr[ci]);
    ci = tA-1<0?0:(tA-1>NT?NT:tA-1); x1 = __ldg(&pxr[ci]);
    ci = tA-1<0?0:(tA-1>NT-1?NT-1:tA-1); y1 = __ldg(&pyr[ci]);
    for(int d=0; d<=NS+NT; ++d){
      int t = NT - d + (NS - s);
      int tp = t-2;
      ci = tp<0?0:(tp>NT?NT:tp);         x2 = __ldg(&pxr[ci]);
      ci = tp<0?0:(tp>NT-1?NT-1:tp);     y2 = __ldg(&pyr[ci]);
      float np = p;
      if(t>=0 && t<=NT){
        if(s==NS && t==NT) np = 0.f;
        else{
          float v1 = hasx ? buf[d&1][s+1] + x0 : NEGF;
          float v2 = (t<NT) ? p + y0 : NEGF;
          np = lae2(v1,v2);
        }
        BE[(size_t)s*NT1+t] = np;
      }
      buf[(d+1)&1][s] = np;
      p = np;
      x0=x1; x1=x2; y0=y1; y1=y2;
      __syncthreads();
    }
  }
}

// ---------------- occupancy grads (merged) ----------------
__global__ void k_grads(){
  int idx = blockIdx.x*blockDim.x + threadIdx.x;
  const int N1 = NB*NS*NT1;
  if(idx < N1){
    int t = idx % NT1; int s = (idx/NT1) % NS; int b = idx/(NS*NT1);
    float a  = g_alpha[((size_t)b*NS1+s)*NT1 + t];
    float be = g_beta [((size_t)b*NS1+s+1)*NT1 + t];
    g_pxg[idx] = expf(a + g_px[idx] + be - g_total[b]);
  } else {
    int k = idx - N1;
    if(k >= NB*NS1*NT) return;
    int t = k % NT; int s = (k/NT) % NS1; int b = k/(NS1*NT);
    float a  = g_alpha[((size_t)b*NS1+s)*NT1 + t];
    float be = g_beta [((size_t)b*NS1+s)*NT1 + t + 1];
    g_pyg[k] = expf(a + g_py[k] + be - g_total[b]);
  }
}

// ---------------- pruning window argmax ----------------
__global__ void k_sbegin(){
  int idx = blockIdx.x*blockDim.x + threadIdx.x;
  if(idx >= NB*NT) return;
  int b = idx / NT, t = idx % NT;
  float U[NS1+1];
  U[0] = 0.f;
  for(int s=0;s<=NS;s++){
    float u = g_pyg[((size_t)b*NS1+s)*NT + t];
    if(s < NS) u += g_pxg[((size_t)b*NS+s)*NT1 + t];
    U[s+1] = U[s] + u;
  }
  float best = -3.4e38f; int arg = 0;
  for(int w=0; w<=NS1-RR; w++){
    float v = U[w+RR] - U[w];
    if(v > best){ best = v; arg = w; }
  }
  g_sb[idx] = arg;
}

__global__ void k_adjust(){
  int b = threadIdx.x;
  if(b >= NB) return;
  int m = 1<<30, ym = 1<<30;
  for(int t=NT-1; t>=0; --t){
    int v = g_sb[b*NT+t];
    m = min(m, v);
    int y = (RR-1)*t - m;
    ym = min(ym, y);
    int yc = max(ym, 0);
    g_sb[b*NT+t] = (RR-1)*t - yc;
  }
}

// ---------------- joiner band build (tanh.approx, bf16x2 stores) ------------
__global__ void k_buildA(const float* __restrict__ am, const float* __restrict__ lm){
  int b = blockIdx.x / NT, t = blockIdx.x % NT;
  __shared__ float amr[NC];
  for(int c=threadIdx.x;c<NC;c+=256) amr[c]=am[((size_t)b*NT+t)*NC+c];
  __syncthreads();
  int sb = g_sb[b*NT+t];
  size_t base = (size_t)(b*NT+t)*RR;
  int c = threadIdx.x*2;
  for(int j=0;j<RR;j++){
    const float* lr = lm + ((size_t)(b*NS1 + sb + j))*NC;
    float2 lv = *(const float2*)&lr[c];
    __nv_bfloat162 o;
    o.x = __float2bfloat16(tanh_ap(amr[c]   + lv.x));
    o.y = __float2bfloat16(tanh_ap(amr[c+1] + lv.y));
    *(__nv_bfloat162*)&g_A[(base+j)*NC + c] = o;
  }
}

// ---- joiner GEMM + fused band epilogue -------------------------------------
#define AP 40
#define BP 136
#define AST (128*AP)
#define BST (32*BP)
__global__ void __launch_bounds__(256) k_gemm(const int* __restrict__ tg,
                                              const float* __restrict__ bias){
  __shared__ __align__(16) char sbuf[(2*AST + 2*BST)*2];
  __nv_bfloat16* As = (__nv_bfloat16*)sbuf;
  __nv_bfloat16* Bs = (__nv_bfloat16*)(sbuf + 2*AST*2);
  int bn = blockIdx.x*128, bm = blockIdx.y*128;
  int tid = threadIdx.x, warp = tid>>5, lane = tid&31;
  int wm = warp & 1, wn = warp >> 1;
  uint32_t asb = (uint32_t)__cvta_generic_to_shared(As);
  uint32_t bsb = (uint32_t)__cvta_generic_to_shared(Bs);

  wmma::fragment<wmma::accumulator,16,16,16,float> acc[4][2];
  #pragma unroll
  for(int i=0;i<4;i++)
    #pragma unroll
    for(int j=0;j<2;j++) wmma::fill_fragment(acc[i][j], 0.f);

  auto loadst = [&](int ki, int st){
    #pragma unroll
    for(int it=0;it<2;it++){
      int v = tid + it*256, row = v>>2, q = v&3;
      cp16(asb + (st*AST + row*AP)*2 + q*16,
           &g_A[(size_t)(bm+row)*NC + ki*32 + q*8]);
    }
    #pragma unroll
    for(int it=0;it<2;it++){
      int v = tid + it*256, row = v>>4, q = v&15;
      cp16(bsb + (st*BST + row*BP)*2 + q*16,
           &g_W[(size_t)(ki*32+row)*NC + bn + q*8]);
    }
    asm volatile("cp.async.commit_group;");
  };

  loadst(0,0);
  for(int k=0;k<16;k++){
    int cur = k&1;
    if(k<15){
      loadst(k+1, cur^1);
      asm volatile("cp.async.wait_group 1;");
    } else {
      asm volatile("cp.async.wait_group 0;");
    }
    __syncthreads();
    __nv_bfloat16* Ac = As + cur*AST;
    __nv_bfloat16* Bc = Bs + cur*BST;
    #pragma unroll
    for(int kk=0;kk<2;kk++){
      wmma::fragment<wmma::matrix_a,16,16,16,__nv_bfloat16,wmma::row_major> a[4];
      wmma::fragment<wmma::matrix_b,16,16,16,__nv_bfloat16,wmma::row_major> bfr[2];
      #pragma unroll
      for(int i=0;i<4;i++) wmma::load_matrix_sync(a[i], &Ac[(wm*64+i*16)*AP + kk*16], AP);
      #pragma unroll
      for(int j=0;j<2;j++) wmma::load_matrix_sync(bfr[j], &Bc[(kk*16)*BP + wn*32 + j*16], BP);
      #pragma unroll
      for(int i=0;i<4;i++)
        #pragma unroll
        for(int j=0;j<2;j++) wmma::mma_sync(acc[i][j], a[i], bfr[j], acc[i][j]);
    }
    __syncthreads();
  }

  // fused band epilogue: per-block partial logsumexp + target/blank extraction
  float* Sg = (float*)sbuf;
  #pragma unroll
  for(int ph=0; ph<2; ph++){
    if(wm == ph){
      #pragma unroll
      for(int i=0;i<4;i++)
        #pragma unroll
        for(int j=0;j<2;j++)
          wmma::store_matrix_sync(&Sg[(i*16)*132 + wn*32 + j*16], acc[i][j], 132,
                                  wmma::mem_row_major);
    }
    __syncthreads();
    #pragma unroll
    for(int q=0;q<8;q++){
      int r = warp*8 + q;
      float4 v4 = *(float4*)&Sg[r*132 + lane*4];
      float4 b4 = *(const float4*)&bias[bn + lane*4];
      float x0=v4.x+b4.x, x1=v4.y+b4.y, x2=v4.z+b4.z, x3=v4.w+b4.w;
      float mx = warpmax(fmaxf(fmaxf(x0,x1),fmaxf(x2,x3)));
      float ss = warpsum(expf(x0-mx)+expf(x1-mx)+expf(x2-mx)+expf(x3-mx));
      if(lane==0){
        int gr = bm + ph*64 + r;
        g_pmax[(size_t)gr*4 + blockIdx.x] = mx;
        g_psum[(size_t)gr*4 + blockIdx.x] = ss;
        int j = gr % RR; int bt = gr/RR; int b = bt/NT;
        int rng = g_sb[bt] + j;
        int sym = (rng < NS) ? tg[b*NS + rng] : 0;
        int sc = sym - bn;
        if(sc >= 0 && sc < 128) g_pxv[gr] = Sg[r*132 + sc] + bias[sym];
        if(bn == 0)             g_pyv[gr] = Sg[r*132]      + bias[0];
      }
    }
    __syncthreads();
  }
}

// ------- scatter band to full lattice, combining N-partial lse inline -------
__device__ __forceinline__ float band_lse(int gr){
  float4 m4 = *(const float4*)&g_pmax[(size_t)gr*4];
  float4 s4 = *(const float4*)&g_psum[(size_t)gr*4];
  float M = fmaxf(fmaxf(m4.x,m4.y), fmaxf(m4.z,m4.w));
  float S = s4.x*expf(m4.x-M) + s4.y*expf(m4.y-M) + s4.z*expf(m4.z-M) + s4.w*expf(m4.w-M);
  return M + logf(S);
}
__global__ void k_scatter(){
  int idx = blockIdx.x*blockDim.x + threadIdx.x;
  const int N1 = NB*NS*NT1;
  if(idx < N1){
    int t = idx % NT1; int s = (idx/NT1) % NS; int b = idx/(NS*NT1);
    float v = NEGF;
    if(t < NT){
      int sb = g_sb[b*NT+t]; int j = s - sb;
      if(j>=0 && j<RR){
        int gr = (b*NT+t)*RR + j;
        v = g_pxv[gr] - band_lse(gr);
      }
    }
    g_pxf[idx] = v;
  } else {
    int k = idx - N1;
    if(k >= NB*NS1*NT) return;
    int t = k % NT; int s = (k/NT) % NS1; int b = k/(NS1*NT);
    int sb = g_sb[b*NT+t]; int j = s - sb;
    float v = NEGF;
    if(j>=0 && j<RR){
      int gr = (b*NT+t)*RR + j;
      v = g_pyv[gr] - band_lse(gr);
    }
    g_pyf[k] = v;
  }
}

// ---------------- final loss ----------------
__global__ void k_final(float* out){
  float a=0.f, c=0.f;
  for(int b=0;b<NB;b++){ a += g_total[b]; c += g_total2[b]; }
  out[0] = -(0.1f*a + c)/(float)NB;
}

extern "C" void kernel_launch(void* const* d_in, const int* in_sizes, int n_in,
                              void* d_out, int out_size) {
  const float* am  = (const float*)d_in[0];
  const float* lm  = (const float*)d_in[1];
  const int*   tg  = (const int*)  d_in[2];
  const float* jw  = (const float*)d_in[4];
  const float* jb  = (const float*)d_in[5];
  float* out = (float*)d_out;
  (void)in_sizes; (void)n_in; (void)out_size;

  const int NPXY = NB*NS*NT1 + NB*NS1*NT;

  k_stats<<<(NB*NS1 + NB*NT + 7)/8, 256>>>(lm, am);     // 0
  k_norm<<<dim3(NT/64, 3, NB), 256>>>(am, lm, tg);      // 1
  k_convW<<<(NC*NC+255)/256, 256>>>(jw);                // 2
  k_dp<<<dim3(NB,2), NS1>>>(0);                         // 3  <- profiled slot
  k_grads<<<(NPXY+255)/256, 256>>>();                   // 4
  k_sbegin<<<(NB*NT+255)/256, 256>>>();                 // 5
  k_adjust<<<1, NB>>>();                                // 6
  k_buildA<<<NB*NT, 256>>>(am, lm);                     // 7
  k_gemm<<<dim3(4, MROWS/128), 256>>>(tg, jb);          // 8
  k_scatter<<<(NPXY+255)/256, 256>>>();                 // 9
  k_dp<<<dim3(NB,1), NS1>>>(1);                         // 10
  k_final<<<1,1>>>(out);                                // 11
}